// round 4
// baseline (speedup 1.0000x reference)
#include <cuda_runtime.h>
#include <cstdint>

#define NQ 4
#define NL 8

typedef unsigned long long u64;

// 27 groups (a*9+b*3+c) x 4 floats (d=0..2, pad). Written by setup, read by main.
__device__ __align__(16) float g_T[112];

__device__ __forceinline__ float2 cmul(float2 a, float2 b) {
    return make_float2(fmaf(a.x, b.x, -a.y * b.y), fmaf(a.x, b.y, a.y * b.x));
}
__device__ __forceinline__ float2 cfma(float2 a, float2 b, float2 acc) {
    acc.x = fmaf(a.x, b.x, fmaf(-a.y, b.y, acc.x));
    acc.y = fmaf(a.x, b.y, fmaf(a.y, b.x, acc.y));
    return acc;
}

// packed f32x2 helpers (ptxas never auto-fuses; must be PTX)
__device__ __forceinline__ u64 pk(float lo, float hi) {
    u64 r; asm("mov.b64 %0, {%1,%2};" : "=l"(r) : "f"(lo), "f"(hi)); return r;
}
__device__ __forceinline__ void upk(u64 v, float& lo, float& hi) {
    asm("mov.b64 {%0,%1}, %2;" : "=f"(lo), "=f"(hi) : "l"(v));
}
__device__ __forceinline__ u64 fma2(u64 a, u64 b, u64 c) {
    u64 d; asm("fma.rn.f32x2 %0, %1, %2, %3;" : "=l"(d) : "l"(a), "l"(b), "l"(c)); return d;
}

// CNOT state-index map: flips target bit if control bit set.
__device__ __forceinline__ int cnot_map(int m, int c, int t) {
    int bc = 3 - c, bt = 3 - t;
    if ((m >> bc) & 1) m ^= (1 << bt);
    return m;
}

// One block, 256 threads. Builds the 81-coefficient multilinear tensor T from weights.
__global__ void vqc_setup(const float* __restrict__ w) {
    __shared__ float2 sGate[NL * NQ][4];   // 2x2 Rot matrices
    __shared__ float2 sPA[NL][16];         // g(w0) (x) g(w1), per layer
    __shared__ float2 sPB[NL][16];         // g(w2) (x) g(w3), per layer
    __shared__ float2 sUa[256], sUb[256];  // U[col][m] ping-pong
    __shared__ float  sG[256];             // real G reindexed by wire pair-codes
    __shared__ float  sA1[192], sA2[144];  // Tucker staging

    const int t = threadIdx.x;

    // ---- phase 0: gate matrices (t<32) + identity init ----
    if (t < NL * NQ) {
        float phi = w[t * 3 + 0], th = w[t * 3 + 1], om = w[t * 3 + 2];
        float st, ct; __sincosf(0.5f * th, &st, &ct);
        float a = 0.5f * (phi + om), b = 0.5f * (phi - om);
        float sa, ca, sb, cb;
        __sincosf(a, &sa, &ca);
        __sincosf(b, &sb, &cb);
        sGate[t][0] = make_float2(ca * ct, -sa * ct);   // m00 = e^{-ia} ct
        sGate[t][1] = make_float2(-cb * st, -sb * st);  // m01 = -e^{+ib} st
        sGate[t][2] = make_float2(cb * st, -sb * st);   // m10 = e^{-ib} st
        sGate[t][3] = make_float2(ca * ct, sa * ct);    // m11 = e^{+ia} ct
    }
    {
        int col = t >> 4, m = t & 15;
        sUa[t] = make_float2(col == m ? 1.0f : 0.0f, 0.0f);
    }
    __syncthreads();

    // ---- phase 1: pair Kronecker factors, one entry per thread ----
    {
        int l = t >> 5, r = t & 31;
        int which = r >> 4, idx = r & 15;
        int i = idx >> 2, j = idx & 3;
        const float2* gA = sGate[l * 4 + which * 2 + 0];
        const float2* gB = sGate[l * 4 + which * 2 + 1];
        float2 v = cmul(gA[(i >> 1) * 2 + (j >> 1)], gB[(i & 1) * 2 + (j & 1)]);
        if (which) sPB[l][idx] = v; else sPA[l][idx] = v;
    }
    __syncthreads();

    // ---- phase 2: 8 layers, 1 sync each; CNOT permutation folded into write ----
    float2* cur = sUa;
    float2* nxt = sUb;
    const int col = t >> 4, m = t & 15;
    const int mh = m >> 2, ml = m & 3;
    int mp = m;
    mp = cnot_map(mp, 0, 1);
    mp = cnot_map(mp, 1, 2);
    mp = cnot_map(mp, 2, 3);
    mp = cnot_map(mp, 3, 0);
    for (int l = 0; l < NL; l++) {
        float2 acc = make_float2(0.0f, 0.0f);
#pragma unroll
        for (int nh = 0; nh < 4; nh++) {
            float2 inner = make_float2(0.0f, 0.0f);
#pragma unroll
            for (int nl = 0; nl < 4; nl++)
                inner = cfma(sPB[l][ml * 4 + nl], cur[col * 16 + nh * 4 + nl], inner);
            acc = cfma(sPA[l][mh * 4 + nh], inner, acc);
        }
        nxt[col * 16 + mp] = acc;
        __syncthreads();
        float2* tmp = cur; cur = nxt; nxt = tmp;
    }

    // ---- phase 3: H = U^dag Z0 U, phase-fold to real G ----
    {
        int j = t >> 4, k = t & 15;
        float hr = 0.0f, hi = 0.0f;
#pragma unroll
        for (int mm = 0; mm < 16; mm++) {
            float zz = ((mm >> 3) & 1) ? -1.0f : 1.0f;
            float2 uj = cur[j * 16 + mm], uk = cur[k * 16 + mm];
            hr += zz * (uj.x * uk.x + uj.y * uk.y);
            hi += zz * (uj.x * uk.y - uj.y * uk.x);
        }
        int q = (__popc(j) - __popc(k)) & 3;  // i^q * H, take Re
        float gval = (q == 0) ? hr : (q == 1) ? -hi : (q == 2) ? -hr : hi;
        int gidx = 0;
#pragma unroll
        for (int wq = 0; wq < 4; wq++) {
            int bi = 3 - wq;
            int p = ((j >> bi) & 1) * 2 + ((k >> bi) & 1);
            gidx = gidx * 4 + p;
        }
        sG[gidx] = gval;
    }
    __syncthreads();

    // ---- phase 4: Tucker contract each wire's pair-code (4) with V (4x3) ----
    const float V[4][3] = {{0.5f, 0.5f, 0.0f},
                           {0.0f, 0.0f, 0.5f},
                           {0.0f, 0.0f, 0.5f},
                           {0.5f, -0.5f, 0.0f}};
    if (t < 192) {  // A1[p0][p1][p2][d]
        int d = t % 3, p2 = (t / 3) & 3, p1 = (t / 12) & 3, p0 = t / 48;
        float acc = 0.0f;
#pragma unroll
        for (int p3 = 0; p3 < 4; p3++)
            acc += sG[((p0 * 4 + p1) * 4 + p2) * 4 + p3] * V[p3][d];
        sA1[t] = acc;
    }
    __syncthreads();
    if (t < 144) {  // A2[p0][p1][c][d]
        int d = t % 3, c = (t / 3) % 3, rest = t / 9;
        int p1 = rest & 3, p0 = rest >> 2;
        float acc = 0.0f;
#pragma unroll
        for (int p2 = 0; p2 < 4; p2++)
            acc += sA1[((p0 * 4 + p1) * 4 + p2) * 3 + d] * V[p2][c];
        sA2[t] = acc;
    }
    __syncthreads();
    if (t < 108) {  // A3[p0][b][c][d] (reuse sA1)
        int d = t % 3, c = (t / 3) % 3, b = (t / 9) % 3, p0 = t / 27;
        float acc = 0.0f;
#pragma unroll
        for (int p1 = 0; p1 < 4; p1++)
            acc += sA2[((p0 * 4 + p1) * 3 + c) * 3 + d] * V[p1][b];
        sA1[t] = acc;
    }
    __syncthreads();
    if (t < 81) {  // T[a][b][c][d] -> g_T[(a*9+b*3+c)*4 + d]
        int d = t % 3, c = (t / 3) % 3, b = (t / 9) % 3, a = t / 27;
        float acc = 0.0f;
#pragma unroll
        for (int p0 = 0; p0 < 4; p0++)
            acc += sA1[((p0 * 3 + b) * 3 + c) * 3 + d] * V[p0][a];
        g_T[(a * 9 + b * 3 + c) * 4 + d] = acc;
    } else if (t < 108) {
        g_T[(t - 81) * 4 + 3] = 0.0f;  // pad lanes
    }
}

// Main: E = sum T[a,b,c,d] f0[a] f1[b] f2[c] f3[d], f = (1, cos x, sin x).
// 4 consecutive samples per thread, evaluated as 2 packed f32x2 pairs.
// T coefficients pre-duplicated into both lanes (shared, broadcast LDS.128);
// sample angles packed across the two lanes.
__global__ void __launch_bounds__(256, 3) vqc_main(const float4* __restrict__ x,
                                                   float* __restrict__ out, int n) {
    // sDup[u][j]: scalar m[u][j] duplicated into both f32 lanes; j=9 pad.
    // m[u][j] with j = c*3+d  ->  g_T[(u*3+c)*4+d]
    __shared__ __align__(16) u64 sDup[9][10];
    if (threadIdx.x < 90) {
        int u = threadIdx.x / 10, j = threadIdx.x % 10;
        float v = (j < 9) ? g_T[(u * 3 + j / 3) * 4 + (j % 3)] : 0.0f;
        sDup[u][j] = pk(v, v);
    }
    __syncthreads();

    const int q = blockIdx.x * 256 + threadIdx.x;
    const int base = q * 4;
    if (base >= n) return;
    const bool full = (base + 3 < n);

    // ---- prologue: load 4 samples, sincos wires 2,3 packed; save x0,x1 raw ----
    float x0[4], x1[4];
    u64 c2p[2], s2p[2], c3p[2], s3p[2];
#pragma unroll
    for (int p = 0; p < 2; p++) {
        float4 va, vb;
        if (full) {
            va = x[base + 2 * p];
            vb = x[base + 2 * p + 1];
        } else {
            va = (base + 2 * p < n) ? x[base + 2 * p] : make_float4(0.f, 0.f, 0.f, 0.f);
            vb = (base + 2 * p + 1 < n) ? x[base + 2 * p + 1] : make_float4(0.f, 0.f, 0.f, 0.f);
        }
        x0[2 * p] = va.x; x1[2 * p] = va.y;
        x0[2 * p + 1] = vb.x; x1[2 * p + 1] = vb.y;
        float s2a, c2a, s2b, c2b, s3a, c3a, s3b, c3b;
        __sincosf(va.z, &s2a, &c2a);
        __sincosf(vb.z, &s2b, &c2b);
        __sincosf(va.w, &s3a, &c3a);
        __sincosf(vb.w, &s3b, &c3b);
        c2p[p] = pk(c2a, c2b); s2p[p] = pk(s2a, s2b);
        c3p[p] = pk(c3a, c3b); s3p[p] = pk(s3a, s3b);
    }

    // ---- contraction over wires 3,2: fully packed ----
    u64 r9[2][9];
#pragma unroll
    for (int u = 0; u < 9; u++) {
        const ulonglong2* row = reinterpret_cast<const ulonglong2*>(sDup[u]);
        ulonglong2 q0 = row[0];  // {m0, m1}
        ulonglong2 q1 = row[1];  // {m2, m3}
        ulonglong2 q2 = row[2];  // {m4, m5}
        ulonglong2 q3 = row[3];  // {m6, m7}
        u64 j8 = sDup[u][8];     //  m8
#pragma unroll
        for (int p = 0; p < 2; p++) {
            u64 a0 = fma2(q1.x, s3p[p], fma2(q0.y, c3p[p], q0.x));
            u64 a1 = fma2(q2.y, s3p[p], fma2(q2.x, c3p[p], q1.y));
            u64 a2 = fma2(j8,   s3p[p], fma2(q3.y, c3p[p], q3.x));
            r9[p][u] = fma2(a2, s2p[p], fma2(a1, c2p[p], a0));
        }
    }

    // ---- epilogue: wires 1,0 packed, then store ----
    float4 res;
#pragma unroll
    for (int p = 0; p < 2; p++) {
        float s0a, c0a, s0b, c0b, s1a, c1a, s1b, c1b;
        __sincosf(x0[2 * p],     &s0a, &c0a);
        __sincosf(x0[2 * p + 1], &s0b, &c0b);
        __sincosf(x1[2 * p],     &s1a, &c1a);
        __sincosf(x1[2 * p + 1], &s1b, &c1b);
        u64 c1p = pk(c1a, c1b), s1p = pk(s1a, s1b);
        u64 c0p = pk(c0a, c0b), s0p = pk(s0a, s0b);
        u64 b0 = fma2(r9[p][2], s1p, fma2(r9[p][1], c1p, r9[p][0]));
        u64 b1 = fma2(r9[p][5], s1p, fma2(r9[p][4], c1p, r9[p][3]));
        u64 b2 = fma2(r9[p][8], s1p, fma2(r9[p][7], c1p, r9[p][6]));
        u64 E  = fma2(b2, s0p, fma2(b1, c0p, b0));
        float lo, hi; upk(E, lo, hi);
        if (p == 0) { res.x = lo; res.y = hi; }
        else        { res.z = lo; res.w = hi; }
    }
    if (full) {
        reinterpret_cast<float4*>(out)[q] = res;
    } else {
        float vals[4] = {res.x, res.y, res.z, res.w};
#pragma unroll
        for (int k = 0; k < 4; k++)
            if (base + k < n) out[base + k] = vals[k];
    }
}

extern "C" void kernel_launch(void* const* d_in, const int* in_sizes, int n_in,
                              void* d_out, int out_size) {
    const float* x = (const float*)d_in[0];        // (B, 4)
    const float* w = (const float*)d_in[1];        // (8, 4, 3)
    float* out = (float*)d_out;                    // (B,)
    int n = out_size;                              // B

    vqc_setup<<<1, 256>>>(w);
    int quads = (n + 3) / 4;
    vqc_main<<<(quads + 255) / 256, 256>>>((const float4*)x, out, n);
}